// round 1
// baseline (speedup 1.0000x reference)
#include <cuda_runtime.h>
#include <math.h>

// Problem constants
#define B_  32
#define L_  4096
#define N_  256
#define NS  (B_ * N_)       // 8192 series
#define NC  2048            // complex FFT size (L/2)
#define F_  2049            // rfft bins
#define NFEAT 19

// 128 MB transpose scratch (static device array; no dynamic allocation)
__device__ float g_xt[(size_t)B_ * N_ * L_];

// skewed shared indexing to break power-of-2 bank aliasing
#define PHYS(m) ((m) + ((m) >> 4))

// ---------------------------------------------------------------------------
// Kernel 1: transpose (B, L, N) -> (B, N, L)
// ---------------------------------------------------------------------------
__global__ void transpose_kernel(const float* __restrict__ x, float* __restrict__ xt) {
    __shared__ float tile[32][33];
    int b  = blockIdx.z;
    int l0 = blockIdx.x * 32;
    int n0 = blockIdx.y * 32;
    int tx = threadIdx.x, ty = threadIdx.y;   // 32 x 8

#pragma unroll
    for (int r = 0; r < 32; r += 8) {
        tile[ty + r][tx] = x[((size_t)b * L_ + (l0 + ty + r)) * N_ + (n0 + tx)];
    }
    __syncthreads();
#pragma unroll
    for (int r = 0; r < 32; r += 8) {
        xt[((size_t)b * N_ + (n0 + ty + r)) * L_ + (l0 + tx)] = tile[tx][ty + r];
    }
}

// ---------------------------------------------------------------------------
// Block reduction helpers (256 threads)
// ---------------------------------------------------------------------------
__device__ __forceinline__ float blockSum(float v) {
    __shared__ float rbuf[8];
    __shared__ float rres;
    __syncthreads();
    int lane = threadIdx.x & 31, w = threadIdx.x >> 5;
#pragma unroll
    for (int o = 16; o; o >>= 1) v += __shfl_xor_sync(0xffffffffu, v, o);
    if (lane == 0) rbuf[w] = v;
    __syncthreads();
    if (w == 0) {
        float r = (lane < 8) ? rbuf[lane] : 0.0f;
#pragma unroll
        for (int o = 4; o; o >>= 1) r += __shfl_xor_sync(0xffffffffu, r, o);
        if (lane == 0) rres = r;
    }
    __syncthreads();
    return rres;
}

// argmax with tie -> smaller index (matches jax.lax.top_k ordering)
__device__ __forceinline__ void blockArgMax(float v, int i, float& ov, int& oi) {
    __shared__ float vb[8];
    __shared__ int   ib[8];
    __shared__ float fv;
    __shared__ int   fi;
    __syncthreads();
    int lane = threadIdx.x & 31, w = threadIdx.x >> 5;
#pragma unroll
    for (int o = 16; o; o >>= 1) {
        float v2 = __shfl_xor_sync(0xffffffffu, v, o);
        int   i2 = __shfl_xor_sync(0xffffffffu, i, o);
        if (v2 > v || (v2 == v && i2 < i)) { v = v2; i = i2; }
    }
    if (lane == 0) { vb[w] = v; ib[w] = i; }
    __syncthreads();
    if (w == 0) {
        v = (lane < 8) ? vb[lane] : -3.0e38f;
        i = (lane < 8) ? ib[lane] : (1 << 30);
#pragma unroll
        for (int o = 4; o; o >>= 1) {
            float v2 = __shfl_xor_sync(0xffffffffu, v, o);
            int   i2 = __shfl_xor_sync(0xffffffffu, i, o);
            if (v2 > v || (v2 == v && i2 < i)) { v = v2; i = i2; }
        }
        if (lane == 0) { fv = v; fi = i; }
    }
    __syncthreads();
    ov = fv; oi = fi;
}

// ---------------------------------------------------------------------------
// Kernel 2: per-series features. 1 CTA per (b,n), 256 threads.
// ---------------------------------------------------------------------------
__global__ __launch_bounds__(256)
void feat_kernel(const float* __restrict__ xt, float* __restrict__ out) {
    __shared__ float2 Zs[NC + NC / 16];      // skewed storage, 2176 float2
    __shared__ float  twr[NC / 2];           // 1024 twiddles for W_2048
    __shared__ float  twi[NC / 2];
    __shared__ float  amp[F_];
    __shared__ float  topv[5];
    __shared__ int    topi[5];

    const int tid = threadIdx.x;
    const int s   = blockIdx.x;              // series id = b*N + n
    const float2* __restrict__ xin = ((const float2*)xt) + (size_t)s * NC;

    // ---- load series into smem (packed complex layout == contiguous reals) ----
    float lsum = 0.0f;
    for (int m = tid; m < NC; m += 256) {
        float2 v = xin[m];
        Zs[PHYS(m)] = v;
        lsum += v.x + v.y;
    }
    // twiddle table: twr/twi[j] = exp(-i*pi*j/1024)
    for (int j = tid; j < NC / 2; j += 256) {
        float sj, cj;
        sincosf(-(float)M_PI * (float)j * (1.0f / 1024.0f), &sj, &cj);
        twr[j] = cj; twi[j] = sj;
    }

    const float mean = blockSum(lsum) * (1.0f / (float)L_);   // sync inside

    // helper: x[i] from skewed complex storage
    #define GETX(i) (((i) & 1) ? Zs[((i) >> 1) + ((i) >> 5)].y : Zs[((i) >> 1) + ((i) >> 5)].x)

    // ---- centered moments ----
    float s2 = 0.0f, s3 = 0.0f, s4 = 0.0f;
    for (int i = tid; i < L_; i += 256) {
        float d  = GETX(i) - mean;
        float d2 = d * d;
        s2 += d2; s3 += d2 * d; s4 += d2 * d2;
    }
    s2 = blockSum(s2);
    s3 = blockSum(s3);
    s4 = blockSum(s4);

    const float eps   = 1e-8f;
    const float stdv  = sqrtf(s2 / (float)(L_ - 1));
    const float std_e = stdv + eps;
    const float se2   = std_e * std_e;
    const float skew  = (s3 / (float)L_) / (se2 * std_e + eps);
    const float kurt  = (s4 / (float)L_) / (se2 * se2 + eps) - 3.0f;

    // ---- autocorrelation at fixed lags ----
    const int lags[5] = {1, 3, 6, 12, 24};
    float acc[5] = {0.f, 0.f, 0.f, 0.f, 0.f};
    for (int i = tid; i < L_; i += 256) {
        float d = GETX(i) - mean;
#pragma unroll
        for (int l = 0; l < 5; l++) {
            int ii = i + lags[l];
            if (ii < L_) acc[l] += d * (GETX(ii) - mean);
        }
    }
    float ac[5];
#pragma unroll
    for (int l = 0; l < 5; l++) {
        ac[l] = blockSum(acc[l]) / ((float)(L_ - lags[l]) * se2);
    }

    // ---- 2048-pt complex radix-2 DIF FFT (in place, output bit-reversed) ----
    int tstep = 1;
    for (int half = 1024; half >= 1; half >>= 1, tstep <<= 1) {
        __syncthreads();
        for (int k = tid; k < NC / 2; k += 256) {
            int j  = k & (half - 1);
            int i0 = 2 * k - j;
            int i1 = i0 + half;
            float2 a = Zs[PHYS(i0)];
            float2 b = Zs[PHYS(i1)];
            float2 su = make_float2(a.x + b.x, a.y + b.y);
            float2 di = make_float2(a.x - b.x, a.y - b.y);
            float wr = twr[j * tstep], wi = twi[j * tstep];
            Zs[PHYS(i0)] = su;
            Zs[PHYS(i1)] = make_float2(di.x * wr - di.y * wi, di.x * wi + di.y * wr);
        }
    }
    __syncthreads();

    // ---- unpack real-FFT bins and amplitudes ----
    // X[k] = E[k] + e^{-2pi i k / 4096} * O[k], k = 0..2048
    for (int k = tid; k < F_; k += 256) {
        int k1 = k & (NC - 1);
        int k2 = (NC - k) & (NC - 1);
        float2 A = Zs[PHYS((int)(__brev((unsigned)k1) >> 21))];
        float2 Bc = Zs[PHYS((int)(__brev((unsigned)k2) >> 21))];
        Bc.y = -Bc.y;                                   // conj
        float Ex = 0.5f * (A.x + Bc.x);
        float Ey = 0.5f * (A.y + Bc.y);
        float Odx = A.x - Bc.x;
        float Ody = A.y - Bc.y;
        float Ox =  0.5f * Ody;                         // (-i/2)*(A-conj(B))
        float Oy = -0.5f * Odx;
        float sw, cw;
        sincosf(-(float)M_PI * (float)k * (1.0f / 2048.0f), &sw, &cw);
        float Xr = Ex + cw * Ox - sw * Oy;
        float Xi = Ey + cw * Oy + sw * Ox;
        amp[k] = sqrtf(Xr * Xr + Xi * Xi);
    }
    __syncthreads();

    // ---- top-5 of amp (equivalent to the reference's full level machinery:
    //      deeper-level entries are strictly damped by sigmoid products < 1,
    //      so the final top_k(aggregated,5) == top-5 of raw amp) ----
    for (int t = 0; t < 5; t++) {
        float bv = -3.0e38f; int bi = 1 << 30;
        for (int k = tid; k < F_; k += 256) {
            float a = amp[k];
            if (a > bv || (a == bv && k < bi)) { bv = a; bi = k; }
        }
        float ov; int oi;
        blockArgMax(bv, bi, ov, oi);
        if (tid == 0) { topv[t] = ov; topi[t] = oi; amp[oi] = -1.0f; }
        __syncthreads();
    }

    // ---- write 19 features: [mean, std, skew, kurt, freq*5, ampnorm*5, ac*5] ----
    if (tid == 0) {
        float* o = out + (size_t)s * NFEAT;
        o[0] = mean;
        o[1] = stdv;
        o[2] = skew;
        o[3] = kurt;
        float denom = topv[0] + 2.0f * eps;   // (amp.max()+eps)+eps
#pragma unroll
        for (int t = 0; t < 5; t++) {
            o[4 + t] = (float)topi[t] * (1.0f / (float)L_);
            o[9 + t] = topv[t] / denom;
        }
#pragma unroll
        for (int l = 0; l < 5; l++) o[14 + l] = ac[l];
    }
    #undef GETX
}

// ---------------------------------------------------------------------------
extern "C" void kernel_launch(void* const* d_in, const int* in_sizes, int n_in,
                              void* d_out, int out_size) {
    const float* x = (const float*)d_in[0];
    float* out = (float*)d_out;

    float* xt = nullptr;
    cudaGetSymbolAddress((void**)&xt, g_xt);

    dim3 tgrid(L_ / 32, N_ / 32, B_);
    dim3 tblk(32, 8);
    transpose_kernel<<<tgrid, tblk>>>(x, xt);
    feat_kernel<<<NS, 256>>>(xt, out);
}

// round 7
// speedup vs baseline: 1.9344x; 1.9344x over previous
#include <cuda_runtime.h>
#include <math.h>

// Problem constants
#define B_  32
#define L_  4096
#define N_  256
#define NS  (B_ * N_)       // 8192 series
#define NFEAT 19

// 128 MB transpose scratch (static device array; no dynamic allocation)
__device__ float g_xt[(size_t)B_ * N_ * L_];

// ---------------------------------------------------------------------------
// Kernel 1: transpose (B, L, N) -> (B, N, L)
// ---------------------------------------------------------------------------
__global__ void transpose_kernel(const float* __restrict__ x, float* __restrict__ xt) {
    __shared__ float tile[32][33];
    int b  = blockIdx.z;
    int l0 = blockIdx.x * 32;
    int n0 = blockIdx.y * 32;
    int tx = threadIdx.x, ty = threadIdx.y;   // 32 x 8

#pragma unroll
    for (int r = 0; r < 32; r += 8) {
        tile[ty + r][tx] = x[((size_t)b * L_ + (l0 + ty + r)) * N_ + (n0 + tx)];
    }
    __syncthreads();
#pragma unroll
    for (int r = 0; r < 32; r += 8) {
        xt[((size_t)b * N_ + (n0 + ty + r)) * L_ + (l0 + tx)] = tile[tx][ty + r];
    }
}

// ---------------------------------------------------------------------------
// complex helpers
// ---------------------------------------------------------------------------
__device__ __forceinline__ float2 cadd(float2 a, float2 b) { return make_float2(a.x + b.x, a.y + b.y); }
__device__ __forceinline__ float2 csub(float2 a, float2 b) { return make_float2(a.x - b.x, a.y - b.y); }
__device__ __forceinline__ float2 cmul(float2 a, float2 b) {
    return make_float2(a.x * b.x - a.y * b.y, a.x * b.y + a.y * b.x);
}
__device__ __forceinline__ float2 mulnegi(float2 a) { return make_float2(a.y, -a.x); }  // a * (-i)

// radix-8 DIF butterfly: y_q = sum_j x_j * W_8^{j q}   (in place, v[j] -> y[q])
__device__ __forceinline__ void dif8(float2 v[8]) {
    const float S = 0.70710678118654752f;
    float2 a0 = cadd(v[0], v[4]), a1 = cadd(v[1], v[5]), a2 = cadd(v[2], v[6]), a3 = cadd(v[3], v[7]);
    float2 b0 = csub(v[0], v[4]), b1 = csub(v[1], v[5]), b2 = csub(v[2], v[6]), b3 = csub(v[3], v[7]);
    float2 c0 = cadd(a0, a2), c1 = cadd(a1, a3);
    float2 d0 = csub(a0, a2), d1m = mulnegi(csub(a1, a3));
    float2 y0 = cadd(c0, c1), y4 = csub(c0, c1);
    float2 y2 = cadd(d0, d1m), y6 = csub(d0, d1m);
    float2 t0 = b0;
    float2 t1 = make_float2(S * (b1.x + b1.y), S * (b1.y - b1.x));       // * (1-i)/sqrt2
    float2 t2 = mulnegi(b2);                                            // * -i
    float2 t3 = make_float2(S * (b3.y - b3.x), -S * (b3.x + b3.y));     // * (-1-i)/sqrt2
    float2 e0 = cadd(t0, t2), e1 = cadd(t1, t3);
    float2 f0 = csub(t0, t2), f1m = mulnegi(csub(t1, t3));
    float2 y1 = cadd(e0, e1), y5 = csub(e0, e1);
    float2 y3 = cadd(f0, f1m), y7 = csub(f0, f1m);
    v[0] = y0; v[1] = y1; v[2] = y2; v[3] = y3;
    v[4] = y4; v[5] = y5; v[6] = y6; v[7] = y7;
}

// v[q] *= exp(i*ang*q), each power via DIRECT sincosf (round-1 accuracy class)
__device__ __forceinline__ void twiddle8(float2 v[8], float ang) {
#pragma unroll
    for (int q = 1; q < 8; q++) {
        float s, c;
        sincosf(ang * (float)q, &s, &c);
        v[q] = cmul(v[q], make_float2(c, s));
    }
}

// block sum over 256 threads (leading + trailing syncs inside)
__device__ __forceinline__ float blockSum(float v) {
    __shared__ float rbuf[8];
    __shared__ float rres;
    __syncthreads();
    int lane = threadIdx.x & 31, w = threadIdx.x >> 5;
#pragma unroll
    for (int o = 16; o; o >>= 1) v += __shfl_xor_sync(0xffffffffu, v, o);
    if (lane == 0) rbuf[w] = v;
    __syncthreads();
    if (w == 0) {
        float r = (lane < 8) ? rbuf[lane] : 0.0f;
#pragma unroll
        for (int o = 4; o; o >>= 1) r += __shfl_xor_sync(0xffffffffu, r, o);
        if (lane == 0) rres = r;
    }
    __syncthreads();
    return rres;
}

// block argmax, tie -> smaller index (matches jax.lax.top_k ordering)
__device__ __forceinline__ void blockArgMax(float v, int i, float& ov, int& oi) {
    __shared__ float vb[8];
    __shared__ int   ib[8];
    __shared__ float fv;
    __shared__ int   fi;
    __syncthreads();
    int lane = threadIdx.x & 31, w = threadIdx.x >> 5;
#pragma unroll
    for (int o = 16; o; o >>= 1) {
        float v2 = __shfl_xor_sync(0xffffffffu, v, o);
        int   i2 = __shfl_xor_sync(0xffffffffu, i, o);
        if (v2 > v || (v2 == v && i2 < i)) { v = v2; i = i2; }
    }
    if (lane == 0) { vb[w] = v; ib[w] = i; }
    __syncthreads();
    if (w == 0) {
        v = (lane < 8) ? vb[lane] : -3.0e38f;
        i = (lane < 8) ? ib[lane] : (1 << 30);
#pragma unroll
        for (int o = 4; o; o >>= 1) {
            float v2 = __shfl_xor_sync(0xffffffffu, v, o);
            int   i2 = __shfl_xor_sync(0xffffffffu, i, o);
            if (v2 > v || (v2 == v && i2 < i)) { v = v2; i = i2; }
        }
        if (lane == 0) { fv = v; fi = i; }
    }
    __syncthreads();
    ov = fv; oi = fi;
}

// ---------------------------------------------------------------------------
// Kernel 2: per-series features. 1 CTA per (b,n), 256 threads.
// Register-resident radix-8^3 x 4 FFT with 3 smem exchanges + lane radix-4.
// ---------------------------------------------------------------------------
__global__ __launch_bounds__(256, 4)
void feat_kernel(const float* __restrict__ xt, float* __restrict__ out) {
    // 16-byte aligned: this buffer is accessed through float2* views (STS.64),
    // which trap on 4-mod-8 shared addresses (round-6 "misaligned address").
    __shared__ __align__(16) float sbuf[4608];   // 18 KB exchange buffer
    __shared__ float redbuf[64];      // 8 warps x 8 partials
    __shared__ float red[8];          // sum_d2, sum_d3, sum_d4, P1,P3,P6,P12,P24

    const int tid = threadIdx.x;
    const float2* __restrict__ xin = (const float2*)(xt + (size_t)blockIdx.x * L_);
    float2* Z0 = (float2*)sbuf;
    const float* xs = sbuf;

    // ---- load (coalesced) into smem + registers; accumulate S1 ----
    float2 v[8];
    float s1 = 0.f;
#pragma unroll
    for (int j = 0; j < 8; j++) {
        float2 t = xin[tid + 256 * j];
        v[j] = t;
        Z0[tid + 256 * j] = t;
        s1 += t.x + t.y;
    }

    const float mean = blockSum(s1) * (1.0f / (float)L_);   // syncs inside

    // ---- combined centered pass: moments + lag products (conflict-free) ----
    float s2 = 0.f, s3 = 0.f, s4 = 0.f;
    float p0 = 0.f, p1 = 0.f, p2 = 0.f, p3 = 0.f, p4 = 0.f;
#pragma unroll
    for (int it = 0; it < 16; it++) {
        int i = tid + 256 * it;
        float d  = xs[i] - mean;
        float d2 = d * d;
        s2 += d2; s3 += d2 * d; s4 += d2 * d2;
        if (i + 1  < L_) p0 += d * (xs[i + 1]  - mean);
        if (i + 3  < L_) p1 += d * (xs[i + 3]  - mean);
        if (i + 6  < L_) p2 += d * (xs[i + 6]  - mean);
        if (i + 12 < L_) p3 += d * (xs[i + 12] - mean);
        if (i + 24 < L_) p4 += d * (xs[i + 24] - mean);
    }
    {
        float vals[8] = {s2, s3, s4, p0, p1, p2, p3, p4};
        int lane = tid & 31, w = tid >> 5;
#pragma unroll
        for (int j = 0; j < 8; j++) {
            float x = vals[j];
#pragma unroll
            for (int o = 16; o; o >>= 1) x += __shfl_xor_sync(0xffffffffu, x, o);
            if (lane == 0) redbuf[w * 8 + j] = x;
        }
    }
    __syncthreads();   // also orders: all xs reads done before FFT overwrites sbuf
    if (tid < 8) {
        float r = 0.f;
#pragma unroll
        for (int k = 0; k < 8; k++) r += redbuf[k * 8 + tid];
        red[tid] = r;
    }

    // ==== FFT stage 1: radix-8 over stride 256 (data already in registers) ====
    dif8(v);
    twiddle8(v, -3.14159265358979f * (float)tid * (1.0f / 1024.0f));   // W_2048^{tid*q}
#pragma unroll
    for (int q = 0; q < 8; q++) ((float2*)sbuf)[q * 256 + tid] = v[q];
    __syncthreads();

    // ==== FFT stage 2: 8 x FFT_256, radix-8 over stride 32 ====
    const int q1 = tid >> 5, i2 = tid & 31;
#pragma unroll
    for (int j = 0; j < 8; j++) v[j] = ((float2*)sbuf)[q1 * 256 + i2 + 32 * j];
    dif8(v);
    twiddle8(v, -3.14159265358979f * (float)i2 * (1.0f / 128.0f));     // W_256^{i2*q}
    __syncthreads();
#pragma unroll
    for (int q = 0; q < 8; q++) ((float2*)sbuf)[q1 * 288 + q * 36 + i2] = v[q];
    __syncthreads();

    // ==== FFT stage 3: 64 x FFT_32, radix-8 over stride 4 ====
    const int q2 = (tid >> 2) & 7, i3 = tid & 3;
#pragma unroll
    for (int j = 0; j < 8; j++) v[j] = ((float2*)sbuf)[q1 * 288 + q2 * 36 + i3 + 4 * j];
    dif8(v);
    twiddle8(v, -3.14159265358979f * (float)i3 * (1.0f / 16.0f));      // W_32^{i3*q}

    // ==== FFT stage 4: radix-4 across the lane quad (i3 = lane&3), no smem ====
#pragma unroll
    for (int q = 0; q < 8; q++) {
        float2 z = v[q], o;
        o.x = __shfl_xor_sync(0xffffffffu, z.x, 2);
        o.y = __shfl_xor_sync(0xffffffffu, z.y, 2);
        float2 t;
        if (i3 < 2) t = cadd(z, o);
        else { t = csub(o, z); if (i3 == 3) t = mulnegi(t); }
        float2 o2;
        o2.x = __shfl_xor_sync(0xffffffffu, t.x, 1);
        o2.y = __shfl_xor_sync(0xffffffffu, t.y, 1);
        v[q] = (i3 & 1) ? csub(o2, t) : cadd(t, o2);
    }
    __syncthreads();

    // natural-order skewed SoA store: k = 512*p + 64*q3 + 8*q2 + q1
    float* Zr = sbuf;
    float* Zi = sbuf + 2112;
    const int pp = ((i3 & 1) << 1) | (i3 >> 1);
    const int kbase = 512 * pp + 8 * q2 + q1;
#pragma unroll
    for (int q = 0; q < 8; q++) {
        int k  = kbase + 64 * q;
        int ks = k + (k >> 5);
        Zr[ks] = v[q].x;
        Zi[ks] = v[q].y;
    }
    __syncthreads();

    // ==== unpack rfft amplitudes + per-thread top-5 in registers ====
    float tv[5]; int tk[5];
#pragma unroll
    for (int j = 0; j < 5; j++) { tv[j] = -1.0f; tk[j] = 1 << 30; }

#pragma unroll
    for (int it = 0; it < 8; it++) {
        int k  = tid + 256 * it;
        int k2 = (2048 - k) & 2047;
        int ks = k + (k >> 5), ks2 = k2 + (k2 >> 5);
        float Ar = Zr[ks],  Ai = Zi[ks];
        float Br = Zr[ks2], Bi = -Zi[ks2];
        float Ex = 0.5f * (Ar + Br), Ey = 0.5f * (Ai + Bi);
        float Ox = 0.5f * (Ai - Bi), Oy = -0.5f * (Ar - Br);
        float sw, cw;
        sincosf(-3.14159265358979f * (float)k * (1.0f / 2048.0f), &sw, &cw);  // direct
        float Xr = Ex + cw * Ox - sw * Oy;
        float Xi = Ey + cw * Oy + sw * Ox;
        float a  = sqrtf(Xr * Xr + Xi * Xi);
        float cv = a; int ck = k;
#pragma unroll
        for (int j = 0; j < 5; j++) {
            if (cv > tv[j] || (cv == tv[j] && ck < tk[j])) {
                float t0 = tv[j]; int t1 = tk[j];
                tv[j] = cv; tk[j] = ck; cv = t0; ck = t1;
            }
        }
    }
    if (tid == 0) {   // Nyquist bin k = 2048: X = Re(Z[0]) - Im(Z[0])
        float a = fabsf(Zr[0] - Zi[0]);
        float cv = a; int ck = 2048;
#pragma unroll
        for (int j = 0; j < 5; j++) {
            if (cv > tv[j] || (cv == tv[j] && ck < tk[j])) {
                float t0 = tv[j]; int t1 = tk[j];
                tv[j] = cv; tk[j] = ck; cv = t0; ck = t1;
            }
        }
    }

    // ==== global top-5 merge: 5 block-argmax rounds over list heads ====
    float topv[5]; int topk[5];
#pragma unroll
    for (int r = 0; r < 5; r++) {
        float ov; int oi;
        blockArgMax(tv[0], tk[0], ov, oi);
        topv[r] = ov; topk[r] = oi;
        if (tk[0] == oi) {   // k unique across threads -> unique popper
            tv[0] = tv[1]; tk[0] = tk[1];
            tv[1] = tv[2]; tk[1] = tk[2];
            tv[2] = tv[3]; tk[2] = tk[3];
            tv[3] = tv[4]; tk[3] = tk[4];
            tv[4] = -1.0f; tk[4] = 1 << 30;
        }
    }

    // ==== features ====
    if (tid == 0) {
        const float inv = 1.0f / 4096.0f;
        const float eps = 1e-8f;
        float sumd2 = red[0], sumd3 = red[1], sumd4 = red[2];
        float stdv = sqrtf(sumd2 * (1.0f / 4095.0f));
        float se   = stdv + eps;
        float se2  = se * se;
        float skew = (sumd3 * inv) / (se2 * se + eps);
        float kurt = (sumd4 * inv) / (se2 * se2 + eps) - 3.0f;

        float* o = out + (size_t)blockIdx.x * NFEAT;
        o[0] = mean; o[1] = stdv; o[2] = skew; o[3] = kurt;

        float denom = topv[0] + 2.0f * eps;   // (max_amp + eps) + eps
#pragma unroll
        for (int t = 0; t < 5; t++) {
            o[4 + t] = (float)topk[t] * inv;
            o[9 + t] = topv[t] / denom;
        }
        const int LG[5] = {1, 3, 6, 12, 24};
#pragma unroll
        for (int l = 0; l < 5; l++) {
            o[14 + l] = red[3 + l] / ((float)(4096 - LG[l]) * se2);
        }
    }
}

// ---------------------------------------------------------------------------
extern "C" void kernel_launch(void* const* d_in, const int* in_sizes, int n_in,
                              void* d_out, int out_size) {
    const float* x = (const float*)d_in[0];
    float* out = (float*)d_out;

    float* xt = nullptr;
    cudaGetSymbolAddress((void**)&xt, g_xt);

    dim3 tgrid(L_ / 32, N_ / 32, B_);
    dim3 tblk(32, 8);
    transpose_kernel<<<tgrid, tblk>>>(x, xt);
    feat_kernel<<<NS, 256>>>(xt, out);
}

// round 12
// speedup vs baseline: 2.1136x; 1.0926x over previous
#include <cuda_runtime.h>
#include <math.h>

// Problem constants
#define B_  32
#define L_  4096
#define N_  256
#define NS  (B_ * N_)       // 8192 series
#define NFEAT 19

// 128 MB transpose scratch (static device array; no dynamic allocation)
__device__ float g_xt[(size_t)B_ * N_ * L_];
// skewed twiddle table: g_tw[j + (j>>4)] = exp(-i*pi*j/1024), j = 0..2047
#define TWSZ 2176
__device__ float2 g_tw[TWSZ];

// ---------------------------------------------------------------------------
// Kernel 0: fill twiddle table (runs every launch; deterministic; ~2us)
// ---------------------------------------------------------------------------
__global__ void twiddle_init_kernel() {
    int j = blockIdx.x * 256 + threadIdx.x;   // 0..2047
    float s, c;
    sincosf(-3.14159265358979f * (float)j * (1.0f / 1024.0f), &s, &c);
    g_tw[j + (j >> 4)] = make_float2(c, s);
}

// ---------------------------------------------------------------------------
// Kernel 1: transpose (B, L, N) -> (B, N, L)
// ---------------------------------------------------------------------------
__global__ void transpose_kernel(const float* __restrict__ x, float* __restrict__ xt) {
    __shared__ float tile[32][33];
    int b  = blockIdx.z;
    int l0 = blockIdx.x * 32;
    int n0 = blockIdx.y * 32;
    int tx = threadIdx.x, ty = threadIdx.y;   // 32 x 8

#pragma unroll
    for (int r = 0; r < 32; r += 8) {
        tile[ty + r][tx] = x[((size_t)b * L_ + (l0 + ty + r)) * N_ + (n0 + tx)];
    }
    __syncthreads();
#pragma unroll
    for (int r = 0; r < 32; r += 8) {
        xt[((size_t)b * N_ + (n0 + ty + r)) * L_ + (l0 + tx)] = tile[tx][ty + r];
    }
}

// ---------------------------------------------------------------------------
// complex helpers
// ---------------------------------------------------------------------------
__device__ __forceinline__ float2 cadd(float2 a, float2 b) { return make_float2(a.x + b.x, a.y + b.y); }
__device__ __forceinline__ float2 csub(float2 a, float2 b) { return make_float2(a.x - b.x, a.y - b.y); }
__device__ __forceinline__ float2 cmul(float2 a, float2 b) {
    return make_float2(a.x * b.x - a.y * b.y, a.x * b.y + a.y * b.x);
}
__device__ __forceinline__ float2 mulnegi(float2 a) { return make_float2(a.y, -a.x); }  // a * (-i)

// radix-8 DIF butterfly: y_q = sum_j x_j * W_8^{j q}   (in place, v[j] -> y[q])
__device__ __forceinline__ void dif8(float2 v[8]) {
    const float S = 0.70710678118654752f;
    float2 a0 = cadd(v[0], v[4]), a1 = cadd(v[1], v[5]), a2 = cadd(v[2], v[6]), a3 = cadd(v[3], v[7]);
    float2 b0 = csub(v[0], v[4]), b1 = csub(v[1], v[5]), b2 = csub(v[2], v[6]), b3 = csub(v[3], v[7]);
    float2 c0 = cadd(a0, a2), c1 = cadd(a1, a3);
    float2 d0 = csub(a0, a2), d1m = mulnegi(csub(a1, a3));
    float2 y0 = cadd(c0, c1), y4 = csub(c0, c1);
    float2 y2 = cadd(d0, d1m), y6 = csub(d0, d1m);
    float2 t0 = b0;
    float2 t1 = make_float2(S * (b1.x + b1.y), S * (b1.y - b1.x));       // * (1-i)/sqrt2
    float2 t2 = mulnegi(b2);                                            // * -i
    float2 t3 = make_float2(S * (b3.y - b3.x), -S * (b3.x + b3.y));     // * (-1-i)/sqrt2
    float2 e0 = cadd(t0, t2), e1 = cadd(t1, t3);
    float2 f0 = csub(t0, t2), f1m = mulnegi(csub(t1, t3));
    float2 y1 = cadd(e0, e1), y5 = csub(e0, e1);
    float2 y3 = cadd(f0, f1m), y7 = csub(f0, f1m);
    v[0] = y0; v[1] = y1; v[2] = y2; v[3] = y3;
    v[4] = y4; v[5] = y5; v[6] = y6; v[7] = y7;
}

// v[q] *= W_2048^{step*q} from the skewed shared table
__device__ __forceinline__ void twiddle8_tbl(float2 v[8], const float2* stw, int step) {
#pragma unroll
    for (int q = 1; q < 8; q++) {
        int m = step * q;                 // always < 2048 for our stages
        v[q] = cmul(v[q], stw[m + (m >> 4)]);
    }
}

// block sum over 256 threads (leading + trailing syncs inside)
__device__ __forceinline__ float blockSum(float v) {
    __shared__ float rbuf[8];
    __shared__ float rres;
    __syncthreads();
    int lane = threadIdx.x & 31, w = threadIdx.x >> 5;
#pragma unroll
    for (int o = 16; o; o >>= 1) v += __shfl_xor_sync(0xffffffffu, v, o);
    if (lane == 0) rbuf[w] = v;
    __syncthreads();
    if (w == 0) {
        float r = (lane < 8) ? rbuf[lane] : 0.0f;
#pragma unroll
        for (int o = 4; o; o >>= 1) r += __shfl_xor_sync(0xffffffffu, r, o);
        if (lane == 0) rres = r;
    }
    __syncthreads();
    return rres;
}

// block argmax, tie -> smaller index (matches jax.lax.top_k ordering)
__device__ __forceinline__ void blockArgMax(float v, int i, float& ov, int& oi) {
    __shared__ float vb[8];
    __shared__ int   ib[8];
    __shared__ float fv;
    __shared__ int   fi;
    __syncthreads();
    int lane = threadIdx.x & 31, w = threadIdx.x >> 5;
#pragma unroll
    for (int o = 16; o; o >>= 1) {
        float v2 = __shfl_xor_sync(0xffffffffu, v, o);
        int   i2 = __shfl_xor_sync(0xffffffffu, i, o);
        if (v2 > v || (v2 == v && i2 < i)) { v = v2; i = i2; }
    }
    if (lane == 0) { vb[w] = v; ib[w] = i; }
    __syncthreads();
    if (w == 0) {
        v = (lane < 8) ? vb[lane] : -3.0e38f;
        i = (lane < 8) ? ib[lane] : (1 << 30);
#pragma unroll
        for (int o = 4; o; o >>= 1) {
            float v2 = __shfl_xor_sync(0xffffffffu, v, o);
            int   i2 = __shfl_xor_sync(0xffffffffu, i, o);
            if (v2 > v || (v2 == v && i2 < i)) { v = v2; i = i2; }
        }
        if (lane == 0) { fv = v; fi = i; }
    }
    __syncthreads();
    ov = fv; oi = fi;
}

// ---------------------------------------------------------------------------
// Kernel 2: per-series features. 1 CTA per (b,n), 256 threads.
// Register-resident radix-8^3 x 4 FFT, smem twiddle table, squared-amp top-5.
// ---------------------------------------------------------------------------
__global__ __launch_bounds__(256, 4)
void feat_kernel(const float* __restrict__ xt, float* __restrict__ out) {
    // 16-byte aligned: accessed through float2* views (STS.64)
    __shared__ __align__(16) float sbuf[4608];     // 18 KB exchange buffer
    __shared__ float2 stw[TWSZ];                   // 17 KB skewed twiddle table
    __shared__ float redbuf[64];                   // 8 warps x 8 partials
    __shared__ float red[8];                       // d2,d3,d4,P1,P3,P6,P12,P24

    const int tid = threadIdx.x;
    const float2* __restrict__ xin = (const float2*)(xt + (size_t)blockIdx.x * L_);
    float2* Z0 = (float2*)sbuf;
    const float* xs = sbuf;

    // ---- stage twiddle table (coalesced from L2-resident global) ----
    for (int j = tid; j < TWSZ; j += 256) stw[j] = g_tw[j];

    // ---- load (coalesced) into smem + registers; accumulate S1 ----
    float2 v[8];
    float s1 = 0.f;
#pragma unroll
    for (int j = 0; j < 8; j++) {
        float2 t = xin[tid + 256 * j];
        v[j] = t;
        Z0[tid + 256 * j] = t;
        s1 += t.x + t.y;
    }

    const float mean = blockSum(s1) * (1.0f / (float)L_);   // syncs inside

    // ---- combined centered pass: moments + lag products (conflict-free) ----
    float s2 = 0.f, s3 = 0.f, s4 = 0.f;
    float p0 = 0.f, p1 = 0.f, p2 = 0.f, p3 = 0.f, p4 = 0.f;
#pragma unroll
    for (int it = 0; it < 16; it++) {
        int i = tid + 256 * it;
        float d  = xs[i] - mean;
        float d2 = d * d;
        s2 += d2; s3 += d2 * d; s4 += d2 * d2;
        if (i + 1  < L_) p0 += d * (xs[i + 1]  - mean);
        if (i + 3  < L_) p1 += d * (xs[i + 3]  - mean);
        if (i + 6  < L_) p2 += d * (xs[i + 6]  - mean);
        if (i + 12 < L_) p3 += d * (xs[i + 12] - mean);
        if (i + 24 < L_) p4 += d * (xs[i + 24] - mean);
    }
    {
        float vals[8] = {s2, s3, s4, p0, p1, p2, p3, p4};
        int lane = tid & 31, w = tid >> 5;
#pragma unroll
        for (int j = 0; j < 8; j++) {
            float x = vals[j];
#pragma unroll
            for (int o = 16; o; o >>= 1) x += __shfl_xor_sync(0xffffffffu, x, o);
            if (lane == 0) redbuf[w * 8 + j] = x;
        }
    }
    __syncthreads();   // orders: all xs reads done before FFT overwrites sbuf
    if (tid < 8) {
        float r = 0.f;
#pragma unroll
        for (int k = 0; k < 8; k++) r += redbuf[k * 8 + tid];
        red[tid] = r;
    }

    // ==== FFT stage 1: radix-8 over stride 256 ====  W_2048^{tid*q}
    dif8(v);
    twiddle8_tbl(v, stw, tid);
#pragma unroll
    for (int q = 0; q < 8; q++) ((float2*)sbuf)[q * 256 + tid] = v[q];
    __syncthreads();

    // ==== FFT stage 2: 8 x FFT_256, radix-8 over stride 32 ====  W_256^{i2*q} = W_2048^{8*i2*q}
    const int q1 = tid >> 5, i2 = tid & 31;
#pragma unroll
    for (int j = 0; j < 8; j++) v[j] = ((float2*)sbuf)[q1 * 256 + i2 + 32 * j];
    dif8(v);
    twiddle8_tbl(v, stw, 8 * i2);
    __syncthreads();
#pragma unroll
    for (int q = 0; q < 8; q++) ((float2*)sbuf)[q1 * 288 + q * 36 + i2] = v[q];
    __syncthreads();

    // ==== FFT stage 3: 64 x FFT_32, radix-8 over stride 4 ====  W_32^{i3*q} = W_2048^{64*i3*q}
    const int q2 = (tid >> 2) & 7, i3 = tid & 3;
#pragma unroll
    for (int j = 0; j < 8; j++) v[j] = ((float2*)sbuf)[q1 * 288 + q2 * 36 + i3 + 4 * j];
    dif8(v);
    twiddle8_tbl(v, stw, 64 * i3);

    // ==== FFT stage 4: radix-4 across the lane quad (i3 = lane&3), no smem ====
#pragma unroll
    for (int q = 0; q < 8; q++) {
        float2 z = v[q], o;
        o.x = __shfl_xor_sync(0xffffffffu, z.x, 2);
        o.y = __shfl_xor_sync(0xffffffffu, z.y, 2);
        float2 t;
        if (i3 < 2) t = cadd(z, o);
        else { t = csub(o, z); if (i3 == 3) t = mulnegi(t); }
        float2 o2;
        o2.x = __shfl_xor_sync(0xffffffffu, t.x, 1);
        o2.y = __shfl_xor_sync(0xffffffffu, t.y, 1);
        v[q] = (i3 & 1) ? csub(o2, t) : cadd(t, o2);
    }
    __syncthreads();

    // natural-order skewed SoA store: k = 512*p + 64*q3 + 8*q2 + q1
    float* Zr = sbuf;
    float* Zi = sbuf + 2112;
    const int pp = ((i3 & 1) << 1) | (i3 >> 1);
    const int kbase = 512 * pp + 8 * q2 + q1;
#pragma unroll
    for (int q = 0; q < 8; q++) {
        int k  = kbase + 64 * q;
        int ks = k + (k >> 5);
        Zr[ks] = v[q].x;
        Zi[ks] = v[q].y;
    }
    __syncthreads();

    // ==== unpack rfft SQUARED amplitudes + gated per-thread top-5 ====
    float tv[5]; int tk[5];
#pragma unroll
    for (int j = 0; j < 5; j++) { tv[j] = -1.0f; tk[j] = 1 << 30; }

#pragma unroll
    for (int it = 0; it < 8; it++) {
        int k  = tid + 256 * it;
        int k2 = (2048 - k) & 2047;
        int ks = k + (k >> 5), ks2 = k2 + (k2 >> 5);
        float Ar = Zr[ks],  Ai = Zi[ks];
        float Br = Zr[ks2], Bi = -Zi[ks2];
        float Ex = 0.5f * (Ar + Br), Ey = 0.5f * (Ai + Bi);
        float Ox = 0.5f * (Ai - Bi), Oy = -0.5f * (Ar - Br);
        float sw, cw;
        sincosf(-3.14159265358979f * (float)k * (1.0f / 2048.0f), &sw, &cw);  // direct
        float Xr = Ex + cw * Ox - sw * Oy;
        float Xi = Ey + cw * Oy + sw * Ox;
        float a2 = Xr * Xr + Xi * Xi;          // squared amplitude (order-preserving)
        if (a2 > tv[4]) {                       // gate: rarely taken after warmup
            float cv = a2; int ck = k;
#pragma unroll
            for (int j = 0; j < 5; j++) {
                if (cv > tv[j] || (cv == tv[j] && ck < tk[j])) {
                    float t0 = tv[j]; int t1 = tk[j];
                    tv[j] = cv; tk[j] = ck; cv = t0; ck = t1;
                }
            }
        }
    }
    if (tid == 0) {   // Nyquist bin k = 2048: X = Re(Z[0]) - Im(Z[0])
        float d = Zr[0] - Zi[0];
        float a2 = d * d;
        if (a2 > tv[4]) {
            float cv = a2; int ck = 2048;
#pragma unroll
            for (int j = 0; j < 5; j++) {
                if (cv > tv[j] || (cv == tv[j] && ck < tk[j])) {
                    float t0 = tv[j]; int t1 = tk[j];
                    tv[j] = cv; tk[j] = ck; cv = t0; ck = t1;
                }
            }
        }
    }

    // ==== global top-5 merge: 5 block-argmax rounds over list heads ====
    float topv[5]; int topk[5];
#pragma unroll
    for (int r = 0; r < 5; r++) {
        float ov; int oi;
        blockArgMax(tv[0], tk[0], ov, oi);
        topv[r] = ov; topk[r] = oi;
        if (tk[0] == oi) {   // k unique across threads -> unique popper
            tv[0] = tv[1]; tk[0] = tk[1];
            tv[1] = tv[2]; tk[1] = tk[2];
            tv[2] = tv[3]; tk[2] = tk[3];
            tv[3] = tv[4]; tk[3] = tk[4];
            tv[4] = -1.0f; tk[4] = 1 << 30;
        }
    }

    // ==== features ====
    if (tid == 0) {
        const float inv = 1.0f / 4096.0f;
        const float eps = 1e-8f;
        float sumd2 = red[0], sumd3 = red[1], sumd4 = red[2];
        float stdv = sqrtf(sumd2 * (1.0f / 4095.0f));
        float se   = stdv + eps;
        float se2  = se * se;
        float skew = (sumd3 * inv) / (se2 * se + eps);
        float kurt = (sumd4 * inv) / (se2 * se2 + eps) - 3.0f;

        float* o = out + (size_t)blockIdx.x * NFEAT;
        o[0] = mean; o[1] = stdv; o[2] = skew; o[3] = kurt;

        float maxamp = sqrtf(topv[0]);
        float denom  = maxamp + 2.0f * eps;   // (max_amp + eps) + eps
#pragma unroll
        for (int t = 0; t < 5; t++) {
            o[4 + t] = (float)topk[t] * inv;
            o[9 + t] = sqrtf(topv[t]) / denom;
        }
        const int LG[5] = {1, 3, 6, 12, 24};
#pragma unroll
        for (int l = 0; l < 5; l++) {
            o[14 + l] = red[3 + l] / ((float)(4096 - LG[l]) * se2);
        }
    }
}

// ---------------------------------------------------------------------------
extern "C" void kernel_launch(void* const* d_in, const int* in_sizes, int n_in,
                              void* d_out, int out_size) {
    const float* x = (const float*)d_in[0];
    float* out = (float*)d_out;

    float* xt = nullptr;
    cudaGetSymbolAddress((void**)&xt, g_xt);

    twiddle_init_kernel<<<8, 256>>>();
    dim3 tgrid(L_ / 32, N_ / 32, B_);
    dim3 tblk(32, 8);
    transpose_kernel<<<tgrid, tblk>>>(x, xt);
    feat_kernel<<<NS, 256>>>(xt, out);
}

// round 13
// speedup vs baseline: 2.3253x; 1.1001x over previous
#include <cuda_runtime.h>
#include <math.h>

// Problem constants
#define B_  32
#define L_  4096
#define N_  256
#define NS  (B_ * N_)       // 8192 series
#define NFEAT 19

// 128 MB transpose scratch (static device array; no dynamic allocation)
__device__ float g_xt[(size_t)B_ * N_ * L_];
// skewed twiddle table: g_tw[j + (j>>4)] = exp(-i*pi*j/1024), j = 0..2047
#define TWSZ 2176
__device__ float2 g_tw[TWSZ];

// ---------------------------------------------------------------------------
// Kernel 1: transpose (B, L, N) -> (B, N, L); 8 blocks also fill the twiddle
// table (transpose is DRAM-bound, the extra MUFU work rides free).
// ---------------------------------------------------------------------------
__global__ void transpose_kernel(const float* __restrict__ x, float* __restrict__ xt) {
    __shared__ float tile[32][33];
    int b  = blockIdx.z;
    int l0 = blockIdx.x * 32;
    int n0 = blockIdx.y * 32;
    int tx = threadIdx.x, ty = threadIdx.y;   // 32 x 8

    if (blockIdx.z == 0 && blockIdx.y == 0 && blockIdx.x < 8) {
        int j = blockIdx.x * 256 + ty * 32 + tx;   // 0..2047
        float s, c;
        sincosf(-3.14159265358979f * (float)j * (1.0f / 1024.0f), &s, &c);
        g_tw[j + (j >> 4)] = make_float2(c, s);
    }

#pragma unroll
    for (int r = 0; r < 32; r += 8) {
        tile[ty + r][tx] = x[((size_t)b * L_ + (l0 + ty + r)) * N_ + (n0 + tx)];
    }
    __syncthreads();
#pragma unroll
    for (int r = 0; r < 32; r += 8) {
        xt[((size_t)b * N_ + (n0 + ty + r)) * L_ + (l0 + tx)] = tile[tx][ty + r];
    }
}

// ---------------------------------------------------------------------------
// complex helpers
// ---------------------------------------------------------------------------
__device__ __forceinline__ float2 cadd(float2 a, float2 b) { return make_float2(a.x + b.x, a.y + b.y); }
__device__ __forceinline__ float2 csub(float2 a, float2 b) { return make_float2(a.x - b.x, a.y - b.y); }
__device__ __forceinline__ float2 cmul(float2 a, float2 b) {
    return make_float2(a.x * b.x - a.y * b.y, a.x * b.y + a.y * b.x);
}
__device__ __forceinline__ float2 mulnegi(float2 a) { return make_float2(a.y, -a.x); }  // a * (-i)

// radix-8 DIF butterfly: y_q = sum_j x_j * W_8^{j q}   (in place, v[j] -> y[q])
__device__ __forceinline__ void dif8(float2 v[8]) {
    const float S = 0.70710678118654752f;
    float2 a0 = cadd(v[0], v[4]), a1 = cadd(v[1], v[5]), a2 = cadd(v[2], v[6]), a3 = cadd(v[3], v[7]);
    float2 b0 = csub(v[0], v[4]), b1 = csub(v[1], v[5]), b2 = csub(v[2], v[6]), b3 = csub(v[3], v[7]);
    float2 c0 = cadd(a0, a2), c1 = cadd(a1, a3);
    float2 d0 = csub(a0, a2), d1m = mulnegi(csub(a1, a3));
    float2 y0 = cadd(c0, c1), y4 = csub(c0, c1);
    float2 y2 = cadd(d0, d1m), y6 = csub(d0, d1m);
    float2 t0 = b0;
    float2 t1 = make_float2(S * (b1.x + b1.y), S * (b1.y - b1.x));       // * (1-i)/sqrt2
    float2 t2 = mulnegi(b2);                                            // * -i
    float2 t3 = make_float2(S * (b3.y - b3.x), -S * (b3.x + b3.y));     // * (-1-i)/sqrt2
    float2 e0 = cadd(t0, t2), e1 = cadd(t1, t3);
    float2 f0 = csub(t0, t2), f1m = mulnegi(csub(t1, t3));
    float2 y1 = cadd(e0, e1), y5 = csub(e0, e1);
    float2 y3 = cadd(f0, f1m), y7 = csub(f0, f1m);
    v[0] = y0; v[1] = y1; v[2] = y2; v[3] = y3;
    v[4] = y4; v[5] = y5; v[6] = y6; v[7] = y7;
}

// v[q] *= W_2048^{step*q} from the skewed shared table
__device__ __forceinline__ void twiddle8_tbl(float2 v[8], const float2* stw, int step) {
#pragma unroll
    for (int q = 1; q < 8; q++) {
        int m = step * q;                 // always < 2048 for our stages
        v[q] = cmul(v[q], stw[m + (m >> 4)]);
    }
}

// block sum over 256 threads (leading + trailing syncs inside)
__device__ __forceinline__ float blockSum(float v) {
    __shared__ float rbuf[8];
    __shared__ float rres;
    __syncthreads();
    int lane = threadIdx.x & 31, w = threadIdx.x >> 5;
#pragma unroll
    for (int o = 16; o; o >>= 1) v += __shfl_xor_sync(0xffffffffu, v, o);
    if (lane == 0) rbuf[w] = v;
    __syncthreads();
    if (w == 0) {
        float r = (lane < 8) ? rbuf[lane] : 0.0f;
#pragma unroll
        for (int o = 4; o; o >>= 1) r += __shfl_xor_sync(0xffffffffu, r, o);
        if (lane == 0) rres = r;
    }
    __syncthreads();
    return rres;
}

// block argmax, tie -> smaller index (matches jax.lax.top_k ordering)
__device__ __forceinline__ void blockArgMax(float v, int i, float& ov, int& oi) {
    __shared__ float vb[8];
    __shared__ int   ib[8];
    __shared__ float fv;
    __shared__ int   fi;
    __syncthreads();
    int lane = threadIdx.x & 31, w = threadIdx.x >> 5;
#pragma unroll
    for (int o = 16; o; o >>= 1) {
        float v2 = __shfl_xor_sync(0xffffffffu, v, o);
        int   i2 = __shfl_xor_sync(0xffffffffu, i, o);
        if (v2 > v || (v2 == v && i2 < i)) { v = v2; i = i2; }
    }
    if (lane == 0) { vb[w] = v; ib[w] = i; }
    __syncthreads();
    if (w == 0) {
        v = (lane < 8) ? vb[lane] : -3.0e38f;
        i = (lane < 8) ? ib[lane] : (1 << 30);
#pragma unroll
        for (int o = 4; o; o >>= 1) {
            float v2 = __shfl_xor_sync(0xffffffffu, v, o);
            int   i2 = __shfl_xor_sync(0xffffffffu, i, o);
            if (v2 > v || (v2 == v && i2 < i)) { v = v2; i = i2; }
        }
        if (lane == 0) { fv = v; fi = i; }
    }
    __syncthreads();
    ov = fv; oi = fi;
}

// ---------------------------------------------------------------------------
// Kernel 2: per-series features. 1 CTA per (b,n), 256 threads.
// Register-resident radix-8^3 x 4 FFT; all twiddles (stages AND unpack) from
// the shared table; squared-amplitude gated top-5.
// ---------------------------------------------------------------------------
__global__ __launch_bounds__(256, 4)
void feat_kernel(const float* __restrict__ xt, float* __restrict__ out) {
    // 16-byte aligned: accessed through float2* views (STS.64)
    __shared__ __align__(16) float sbuf[4608];     // 18 KB exchange buffer
    __shared__ float2 stw[TWSZ];                   // 17 KB skewed twiddle table
    __shared__ float redbuf[64];                   // 8 warps x 8 partials
    __shared__ float red[8];                       // d2,d3,d4,P1,P3,P6,P12,P24

    const int tid = threadIdx.x;
    const float2* __restrict__ xin = (const float2*)(xt + (size_t)blockIdx.x * L_);
    float2* Z0 = (float2*)sbuf;
    const float* xs = sbuf;

    // ---- stage twiddle table (coalesced from L2-resident global) ----
    for (int j = tid; j < TWSZ; j += 256) stw[j] = g_tw[j];

    // ---- load (coalesced) into smem + registers; accumulate S1 ----
    float2 v[8];
    float s1 = 0.f;
#pragma unroll
    for (int j = 0; j < 8; j++) {
        float2 t = xin[tid + 256 * j];
        v[j] = t;
        Z0[tid + 256 * j] = t;
        s1 += t.x + t.y;
    }

    const float mean = blockSum(s1) * (1.0f / (float)L_);   // syncs inside

    // ---- combined centered pass: moments + lag products (conflict-free) ----
    float s2 = 0.f, s3 = 0.f, s4 = 0.f;
    float p0 = 0.f, p1 = 0.f, p2 = 0.f, p3 = 0.f, p4 = 0.f;
#pragma unroll
    for (int it = 0; it < 16; it++) {
        int i = tid + 256 * it;
        float d  = xs[i] - mean;
        float d2 = d * d;
        s2 += d2; s3 += d2 * d; s4 += d2 * d2;
        if (i + 1  < L_) p0 += d * (xs[i + 1]  - mean);
        if (i + 3  < L_) p1 += d * (xs[i + 3]  - mean);
        if (i + 6  < L_) p2 += d * (xs[i + 6]  - mean);
        if (i + 12 < L_) p3 += d * (xs[i + 12] - mean);
        if (i + 24 < L_) p4 += d * (xs[i + 24] - mean);
    }
    {
        float vals[8] = {s2, s3, s4, p0, p1, p2, p3, p4};
        int lane = tid & 31, w = tid >> 5;
#pragma unroll
        for (int j = 0; j < 8; j++) {
            float x = vals[j];
#pragma unroll
            for (int o = 16; o; o >>= 1) x += __shfl_xor_sync(0xffffffffu, x, o);
            if (lane == 0) redbuf[w * 8 + j] = x;
        }
    }
    __syncthreads();   // orders: all xs reads done before FFT overwrites sbuf
    if (tid < 8) {
        float r = 0.f;
#pragma unroll
        for (int k = 0; k < 8; k++) r += redbuf[k * 8 + tid];
        red[tid] = r;
    }

    // ==== FFT stage 1: radix-8 over stride 256 ====  W_2048^{tid*q}
    dif8(v);
    twiddle8_tbl(v, stw, tid);
#pragma unroll
    for (int q = 0; q < 8; q++) ((float2*)sbuf)[q * 256 + tid] = v[q];
    __syncthreads();

    // ==== FFT stage 2: 8 x FFT_256, radix-8 over stride 32 ====  W_2048^{8*i2*q}
    const int q1 = tid >> 5, i2 = tid & 31;
#pragma unroll
    for (int j = 0; j < 8; j++) v[j] = ((float2*)sbuf)[q1 * 256 + i2 + 32 * j];
    dif8(v);
    twiddle8_tbl(v, stw, 8 * i2);
    __syncthreads();
#pragma unroll
    for (int q = 0; q < 8; q++) ((float2*)sbuf)[q1 * 288 + q * 36 + i2] = v[q];
    __syncthreads();

    // ==== FFT stage 3: 64 x FFT_32, radix-8 over stride 4 ====  W_2048^{64*i3*q}
    const int q2 = (tid >> 2) & 7, i3 = tid & 3;
#pragma unroll
    for (int j = 0; j < 8; j++) v[j] = ((float2*)sbuf)[q1 * 288 + q2 * 36 + i3 + 4 * j];
    dif8(v);
    twiddle8_tbl(v, stw, 64 * i3);

    // ==== FFT stage 4: radix-4 across the lane quad (i3 = lane&3), no smem ====
#pragma unroll
    for (int q = 0; q < 8; q++) {
        float2 z = v[q], o;
        o.x = __shfl_xor_sync(0xffffffffu, z.x, 2);
        o.y = __shfl_xor_sync(0xffffffffu, z.y, 2);
        float2 t;
        if (i3 < 2) t = cadd(z, o);
        else { t = csub(o, z); if (i3 == 3) t = mulnegi(t); }
        float2 o2;
        o2.x = __shfl_xor_sync(0xffffffffu, t.x, 1);
        o2.y = __shfl_xor_sync(0xffffffffu, t.y, 1);
        v[q] = (i3 & 1) ? csub(o2, t) : cadd(t, o2);
    }
    __syncthreads();

    // natural-order skewed SoA store: k = 512*p + 64*q3 + 8*q2 + q1
    float* Zr = sbuf;
    float* Zi = sbuf + 2112;
    const int pp = ((i3 & 1) << 1) | (i3 >> 1);
    const int kbase = 512 * pp + 8 * q2 + q1;
#pragma unroll
    for (int q = 0; q < 8; q++) {
        int k  = kbase + 64 * q;
        int ks = k + (k >> 5);
        Zr[ks] = v[q].x;
        Zi[ks] = v[q].y;
    }
    __syncthreads();

    // ==== unpack rfft SQUARED amplitudes + gated per-thread top-5 ====
    // unpack phase w(k) = exp(-i*pi*k/2048): k parity == tid parity, so
    // w(k) = stw[k>>1] (even tid) or stw[k>>1] * exp(-i*pi/2048) (odd tid).
    const bool  kodd = (tid & 1);
    const float2 uhalf = make_float2(0.99999882345170188f, -0.0015339801862847657f);

    float tv[5]; int tk[5];
#pragma unroll
    for (int j = 0; j < 5; j++) { tv[j] = -1.0f; tk[j] = 1 << 30; }

#pragma unroll
    for (int it = 0; it < 8; it++) {
        int k  = tid + 256 * it;
        int k2 = (2048 - k) & 2047;
        int ks = k + (k >> 5), ks2 = k2 + (k2 >> 5);
        float Ar = Zr[ks],  Ai = Zi[ks];
        float Br = Zr[ks2], Bi = -Zi[ks2];
        float Ex = 0.5f * (Ar + Br), Ey = 0.5f * (Ai + Bi);
        float Ox = 0.5f * (Ai - Bi), Oy = -0.5f * (Ar - Br);
        int h = k >> 1;                               // 0..1023
        float2 w = stw[h + (h >> 4)];
        if (kodd) w = cmul(w, uhalf);
        float Xr = Ex + w.x * Ox - w.y * Oy;
        float Xi = Ey + w.x * Oy + w.y * Ox;
        float a2 = Xr * Xr + Xi * Xi;          // squared amplitude (order-preserving)
        if (a2 > tv[4]) {                       // gate: rarely taken after warmup
            float cv = a2; int ck = k;
#pragma unroll
            for (int j = 0; j < 5; j++) {
                if (cv > tv[j] || (cv == tv[j] && ck < tk[j])) {
                    float t0 = tv[j]; int t1 = tk[j];
                    tv[j] = cv; tk[j] = ck; cv = t0; ck = t1;
                }
            }
        }
    }
    if (tid == 0) {   // Nyquist bin k = 2048: X = Re(Z[0]) - Im(Z[0])
        float d = Zr[0] - Zi[0];
        float a2 = d * d;
        if (a2 > tv[4]) {
            float cv = a2; int ck = 2048;
#pragma unroll
            for (int j = 0; j < 5; j++) {
                if (cv > tv[j] || (cv == tv[j] && ck < tk[j])) {
                    float t0 = tv[j]; int t1 = tk[j];
                    tv[j] = cv; tk[j] = ck; cv = t0; ck = t1;
                }
            }
        }
    }

    // ==== global top-5 merge: 5 block-argmax rounds over list heads ====
    float topv[5]; int topk[5];
#pragma unroll
    for (int r = 0; r < 5; r++) {
        float ov; int oi;
        blockArgMax(tv[0], tk[0], ov, oi);
        topv[r] = ov; topk[r] = oi;
        if (tk[0] == oi) {   // k unique across threads -> unique popper
            tv[0] = tv[1]; tk[0] = tk[1];
            tv[1] = tv[2]; tk[1] = tk[2];
            tv[2] = tv[3]; tk[2] = tk[3];
            tv[3] = tv[4]; tk[3] = tk[4];
            tv[4] = -1.0f; tk[4] = 1 << 30;
        }
    }

    // ==== features ====
    if (tid == 0) {
        const float inv = 1.0f / 4096.0f;
        const float eps = 1e-8f;
        float sumd2 = red[0], sumd3 = red[1], sumd4 = red[2];
        float stdv = sqrtf(sumd2 * (1.0f / 4095.0f));
        float se   = stdv + eps;
        float se2  = se * se;
        float skew = (sumd3 * inv) / (se2 * se + eps);
        float kurt = (sumd4 * inv) / (se2 * se2 + eps) - 3.0f;

        float* o = out + (size_t)blockIdx.x * NFEAT;
        o[0] = mean; o[1] = stdv; o[2] = skew; o[3] = kurt;

        float maxamp = sqrtf(topv[0]);
        float denom  = maxamp + 2.0f * eps;   // (max_amp + eps) + eps
#pragma unroll
        for (int t = 0; t < 5; t++) {
            o[4 + t] = (float)topk[t] * inv;
            o[9 + t] = sqrtf(topv[t]) / denom;
        }
        const int LG[5] = {1, 3, 6, 12, 24};
#pragma unroll
        for (int l = 0; l < 5; l++) {
            o[14 + l] = red[3 + l] / ((float)(4096 - LG[l]) * se2);
        }
    }
}

// ---------------------------------------------------------------------------
extern "C" void kernel_launch(void* const* d_in, const int* in_sizes, int n_in,
                              void* d_out, int out_size) {
    const float* x = (const float*)d_in[0];
    float* out = (float*)d_out;

    float* xt = nullptr;
    cudaGetSymbolAddress((void**)&xt, g_xt);

    dim3 tgrid(L_ / 32, N_ / 32, B_);
    dim3 tblk(32, 8);
    transpose_kernel<<<tgrid, tblk>>>(x, xt);   // also fills g_tw
    feat_kernel<<<NS, 256>>>(xt, out);
}